// round 11
// baseline (speedup 1.0000x reference)
#include <cuda_runtime.h>
#include <cuda_bf16.h>
#include <cstdint>

#define VOCAB 4
#define DIM   128
#define MAX_SEGS 8192
#define CHUNK 16               // tokens per thread; warp covers 512 tokens
#define BLOCK 256
#define FULL  0xFFFFFFFFu

// Per-segment, per-vocab histogram. Zeroed at load; combine_kernel re-zeros
// after consuming -> invariant "all zero on entry" holds every launch/replay.
__device__ int g_counts[MAX_SEGS * VOCAB];

// Flush from bit-sums: s0=Σ(t&1), s1=Σ(t>>1 &1), s3=Σ(t==3).
// n0 = n - s0 - s1 + s3, n1 = s0 - s3, n2 = s1 - s3, n3 = s3.
__device__ __forceinline__ void flush_bits(int seg, int n, int s0, int s1, int s3) {
    if (n == 0) return;
    int n1 = s0 - s3;
    int n2 = s1 - s3;
    int n0 = n - s0 - s1 + s3;
    int* b = &g_counts[seg * VOCAB];
    if (n0) atomicAdd(b + 0, n0);
    if (n1) atomicAdd(b + 1, n1);
    if (n2) atomicAdd(b + 2, n2);
    if (s3) atomicAdd(b + 3, s3);
}

// Legacy flush from (n, ssum=Σt, s0, s3): s1 = (ssum - s0) / 2.
__device__ __forceinline__ void flush_counts(int seg, int n, int ssum, int s0, int s3) {
    flush_bits(seg, n, s0, (ssum - s0) >> 1, s3);
}

// dp4a partial sums for 4 packed tokens (one int4 of token words).
__device__ __forceinline__ void dp4_accum(int4 tk, int& ssum, int& s0, int& s3) {
    unsigned a = __byte_perm((unsigned)tk.x, (unsigned)tk.y, 0x0040);
    unsigned b = __byte_perm((unsigned)tk.z, (unsigned)tk.w, 0x0040);
    unsigned p = __byte_perm(a, b, 0x5410);        // low bytes of 4 tokens
    unsigned u  = p >> 1;
    unsigned b0 = p & 0x01010101u;                 // t & 1
    unsigned b3 = p & u & 0x01010101u;             // t == 3
    ssum = __dp4a((int)p,  0x01010101, ssum);
    s0   = __dp4a((int)b0, 0x01010101, s0);
    s3   = __dp4a((int)b3, 0x01010101, s3);
}

// Warp-ballot accumulation for one token word (warp-uniform segment path).
#define BAL_STEP(TK)                                            \
    do {                                                        \
        unsigned B0 = __ballot_sync(FULL, (TK) & 1);            \
        unsigned B1 = __ballot_sync(FULL, (TK) & 2);            \
        s0 += __popc(B0);                                       \
        s1 += __popc(B1);                                       \
        s3 += __popc(B0 & B1);                                  \
    } while (0)

// Boundary-path step: flush completed run solo, keep current run in registers.
#define HIST_STEP(S, TK)                                        \
    do {                                                        \
        if ((S) != seg) {                                       \
            flush_counts(seg, n, ssum, s0, s3);                 \
            n = 0; ssum = 0; s0 = 0; s3 = 0; seg = (S);         \
        }                                                       \
        n++;                                                    \
        ssum += (TK);                                           \
        s0   += (TK) & 1;                                       \
        s3   += ((TK) == 3);                                    \
    } while (0)

__global__ void __launch_bounds__(BLOCK)
hist_kernel(const int* __restrict__ tokens,
            const int* __restrict__ segids,
            int T) {
    const int chunk_id = blockIdx.x * BLOCK + threadIdx.x;
    const int base = chunk_id * CHUNK;
    const int lane = threadIdx.x & 31;

    // NO early return before warp-collective ops: all 32 lanes participate.
    const bool fullchunk = (base + CHUNK <= T);

    // Scalar segment probes (8 bytes per chunk instead of 32).
    int sA = 0, sB = 0;
    if (fullchunk) {
        sA = __ldg(&segids[base]);
        sB = __ldg(&segids[base + CHUNK - 1]);
    }

    // Warp-uniform test: sorted segids => endpoints equal => all equal.
    bool alluni  = __all_sync(FULL, fullchunk);
    int  first0  = __shfl_sync(FULL, sA, 0);
    int  last31  = __shfl_sync(FULL, sB, 31);

    if (alluni && first0 == last31) {
        // ---- warp-collective ballot path: 512 tokens, one segment ----
        const int4* t4 = (const int4*)(tokens + base);
        int4 t0 = __ldg(&t4[0]), t1 = __ldg(&t4[1]),
             t2 = __ldg(&t4[2]), t3 = __ldg(&t4[3]);
        int s0 = 0, s1 = 0, s3 = 0;
        BAL_STEP(t0.x); BAL_STEP(t0.y); BAL_STEP(t0.z); BAL_STEP(t0.w);
        BAL_STEP(t1.x); BAL_STEP(t1.y); BAL_STEP(t1.z); BAL_STEP(t1.w);
        BAL_STEP(t2.x); BAL_STEP(t2.y); BAL_STEP(t2.z); BAL_STEP(t2.w);
        BAL_STEP(t3.x); BAL_STEP(t3.y); BAL_STEP(t3.z); BAL_STEP(t3.w);
        if (lane == 0)
            flush_bits(first0, 32 * CHUNK, s0, s1, s3);
        return;
    }

    // ---- per-thread path (non-uniform warp, or tail) ----
    int seg = 0, n = 0, ssum = 0, s0 = 0, s3 = 0;

    if (fullchunk) {
        const int4* t4 = (const int4*)(tokens + base);
        int4 t0 = __ldg(&t4[0]), t1 = __ldg(&t4[1]),
             t2 = __ldg(&t4[2]), t3 = __ldg(&t4[3]);
        if (sA == sB) {
            // thread-local fast path: 16 tokens, one segment
            dp4_accum(t0, ssum, s0, s3);
            dp4_accum(t1, ssum, s0, s3);
            dp4_accum(t2, ssum, s0, s3);
            dp4_accum(t3, ssum, s0, s3);
            seg = sA;
            n = CHUNK;
        } else {
            // boundary chunk: need all segids now
            const int4* g4 = (const int4*)(segids + base);
            int4 g0 = __ldg(&g4[0]), g1 = __ldg(&g4[1]),
                 g2 = __ldg(&g4[2]), g3 = __ldg(&g4[3]);
            seg = g0.x;
            HIST_STEP(g0.x, t0.x); HIST_STEP(g0.y, t0.y);
            HIST_STEP(g0.z, t0.z); HIST_STEP(g0.w, t0.w);
            HIST_STEP(g1.x, t1.x); HIST_STEP(g1.y, t1.y);
            HIST_STEP(g1.z, t1.z); HIST_STEP(g1.w, t1.w);
            HIST_STEP(g2.x, t2.x); HIST_STEP(g2.y, t2.y);
            HIST_STEP(g2.z, t2.z); HIST_STEP(g2.w, t2.w);
            HIST_STEP(g3.x, t3.x); HIST_STEP(g3.y, t3.y);
            HIST_STEP(g3.z, t3.z); HIST_STEP(g3.w, t3.w);
        }
    } else if (base < T) {
        // tail chunk (scalar, bounds-checked)
        int end = min(T, base + CHUNK);
        seg = __ldg(&segids[base]);
        for (int i = base; i < end; i++) {
            int s = __ldg(&segids[i]);
            int t = __ldg(&tokens[i]);
            HIST_STEP(s, t);
        }
    }
    // lanes with base >= T carry (seg=0, n=0): they contribute zeros below.

    // ---- Group-aggregated flush: lanes sharing a segment reduce together ----
    unsigned grp = __match_any_sync(FULL, seg);
    int gn    = (int)__reduce_add_sync(grp, (unsigned)n);
    int gssum = (int)__reduce_add_sync(grp, (unsigned)ssum);
    int gs0   = (int)__reduce_add_sync(grp, (unsigned)s0);
    int gs3   = (int)__reduce_add_sync(grp, (unsigned)s3);
    if (lane == (int)(__ffs(grp) - 1))
        flush_counts(seg, gn, gssum, gs0, gs3);
}

// ---------------------------------------------------------------------------
// Combine: one warp per segment, one float4 per lane (32 lanes x 4 = 128 dims).
// ---------------------------------------------------------------------------
__global__ void __launch_bounds__(BLOCK)
combine_kernel(const float* __restrict__ emb,
               float* __restrict__ out, int R) {
    int tid  = blockIdx.x * BLOCK + threadIdx.x;
    int seg  = tid >> 5;
    int lane = tid & 31;
    if (seg >= R) return;

    // Counts first (L2 round-trip overlaps the emb loads below).
    int4 c = *(const int4*)&g_counts[seg * VOCAB];

    const float4* e = (const float4*)emb;
    float4 e0 = __ldg(&e[0 * 32 + lane]);
    float4 e1 = __ldg(&e[1 * 32 + lane]);
    float4 e2 = __ldg(&e[2 * 32 + lane]);
    float4 e3 = __ldg(&e[3 * 32 + lane]);

    float f0 = (float)c.x, f1 = (float)c.y, f2 = (float)c.z, f3 = (float)c.w;
    float inv = 1.0f / fmaxf(f0 + f1 + f2 + f3, 1.0f);

    float4 r;
    r.x = (f0 * e0.x + f1 * e1.x + f2 * e2.x + f3 * e3.x) * inv;
    r.y = (f0 * e0.y + f1 * e1.y + f2 * e2.y + f3 * e3.y) * inv;
    r.z = (f0 * e0.z + f1 * e1.z + f2 * e2.z + f3 * e3.z) * inv;
    r.w = (f0 * e0.w + f1 * e1.w + f2 * e2.w + f3 * e3.w) * inv;
    ((float4*)out)[seg * 32 + lane] = r;

    __syncwarp();
    if (lane == 0)                            // restore zero invariant
        *(int4*)&g_counts[seg * VOCAB] = make_int4(0, 0, 0, 0);
}

extern "C" void kernel_launch(void* const* d_in, const int* in_sizes, int n_in,
                              void* d_out, int out_size) {
    const int* tokens = (const int*)d_in[0];
    const int* segids = (const int*)d_in[1];
    const float* emb  = (const float*)d_in[2];
    float* out        = (float*)d_out;

    int T = in_sizes[0];
    int R = out_size / DIM;

    int nchunks = (T + CHUNK - 1) / CHUNK;
    int grid = (nchunks + BLOCK - 1) / BLOCK;      // one chunk per thread
    if (grid < 1) grid = 1;
    hist_kernel<<<grid, BLOCK>>>(tokens, segids, T);

    int cthreads = R * 32;
    int cgrid = (cthreads + BLOCK - 1) / BLOCK;
    combine_kernel<<<cgrid, BLOCK>>>(emb, out, R);
}